// round 2
// baseline (speedup 1.0000x reference)
#include <cuda_runtime.h>
#include <cuda_bf16.h>
#include <cstdint>

// ---------------------------------------------------------------------------
// GATNet: GATConv(512->4x32,concat)+ELU -> GATConv(128->4x128,mean) -> Linear
// N=100000 nodes, E=600000 edges (+N self loops), H=4 heads.
// Output layout: [ out (N*64) | embeddings (N*128) ]  (reference return order)
// NOTE: edge_index is int32 on disk (JAX x64 disabled downcasts int64->int32).
// ---------------------------------------------------------------------------

#define MAXN 100000
#define MAXE 600000
#define MAXET (MAXE + MAXN)   // edges incl. self loops

// -------------------- scratch (device globals; no allocs) ------------------
__device__ float    g_h1[(size_t)MAXN * 128];    // GEMM1 output  [N, H*C1]
__device__ float    g_hact[(size_t)MAXN * 128];  // layer-1 activated output
__device__ float    g_h2[(size_t)MAXN * 512];    // GEMM2 output  [N, H*C2]
__device__ float    g_agg1[(size_t)MAXN * 128];  // layer-1 unnormalized agg
__device__ float    g_agg2[(size_t)MAXN * 512];  // layer-2 unnormalized agg
__device__ float    g_as[(size_t)MAXN * 4];      // alpha_src per (node, head)
__device__ float    g_ad[(size_t)MAXN * 4];      // alpha_dst per (node, head)
__device__ float    g_esum[(size_t)MAXN * 4];    // softmax denominators
__device__ unsigned g_emax[(size_t)MAXN * 4];    // segment max (ordered-uint)
__device__ float    g_ebuf[(size_t)MAXET * 4];   // per-edge logits / scratch

// Ordered monotone encoding of float into unsigned for atomicMax.
__device__ __forceinline__ unsigned fenc(float f) {
    unsigned u = __float_as_uint(f);
    return (u & 0x80000000u) ? ~u : (u | 0x80000000u);
}
__device__ __forceinline__ float fdec(unsigned u) {
    return (u & 0x80000000u) ? __uint_as_float(u ^ 0x80000000u)
                             : __uint_as_float(~u);
}

// -------------------- zero-init kernels ------------------------------------
__global__ void zero_layer1(int n) {
    int i = blockIdx.x * blockDim.x + threadIdx.x;
    if (i < n * 128) g_agg1[i] = 0.f;
    if (i < n * 4) { g_esum[i] = 0.f; g_emax[i] = 0u; }
}
__global__ void zero_layer2(int n) {
    int i = blockIdx.x * blockDim.x + threadIdx.x;
    if (i < n * 512) g_agg2[i] = 0.f;
    if (i < n * 4) { g_esum[i] = 0.f; g_emax[i] = 0u; }
}

// -------------------- SGEMM: C[M,N] = A[M,K] @ B[K,N] (+bias) --------------
// 128x128 tile, BK=16, 256 threads, 8x8 per-thread microtile.
// Requires K % 16 == 0 and N % 4 == 0 (true here: K in {512,128}, N in {128,512,64}).
__global__ __launch_bounds__(256) void sgemm128(
    const float* __restrict__ A, const float* __restrict__ B,
    const float* __restrict__ bias, float* __restrict__ C,
    int M, int N, int K)
{
    __shared__ float As[16][128];
    __shared__ float Bs[16][128];
    const int tid  = threadIdx.x;
    const int brow = blockIdx.y * 128;
    const int bcol = blockIdx.x * 128;
    const int tr = tid >> 4, tc = tid & 15;
    const int row0 = tr * 8, col0 = tc * 8;

    float acc[8][8];
#pragma unroll
    for (int i = 0; i < 8; i++)
#pragma unroll
        for (int j = 0; j < 8; j++) acc[i][j] = 0.f;

    for (int k0 = 0; k0 < K; k0 += 16) {
        // load A tile (128 rows x 16 cols), transposed into As[k][row]
#pragma unroll
        for (int i = 0; i < 2; i++) {
            int id = tid + i * 256;            // 0..511
            int r  = id >> 2;                  // 0..127
            int c  = (id & 3) << 2;            // 0,4,8,12
            float4 v = make_float4(0.f, 0.f, 0.f, 0.f);
            int gr = brow + r;
            if (gr < M)
                v = *reinterpret_cast<const float4*>(A + (size_t)gr * K + k0 + c);
            As[c + 0][r] = v.x; As[c + 1][r] = v.y;
            As[c + 2][r] = v.z; As[c + 3][r] = v.w;
        }
        // load B tile (16 rows x 128 cols)
#pragma unroll
        for (int i = 0; i < 2; i++) {
            int id = tid + i * 256;
            int r  = id >> 5;                  // 0..15
            int c  = (id & 31) << 2;           // 0..124
            float4 v = make_float4(0.f, 0.f, 0.f, 0.f);
            int gc = bcol + c;
            if (gc < N)
                v = *reinterpret_cast<const float4*>(B + (size_t)(k0 + r) * N + gc);
            *reinterpret_cast<float4*>(&Bs[r][c]) = v;
        }
        __syncthreads();
#pragma unroll
        for (int k = 0; k < 16; k++) {
            float a[8], b[8];
#pragma unroll
            for (int j = 0; j < 8; j++) { a[j] = As[k][row0 + j]; b[j] = Bs[k][col0 + j]; }
#pragma unroll
            for (int i = 0; i < 8; i++)
#pragma unroll
                for (int j = 0; j < 8; j++) acc[i][j] = fmaf(a[i], b[j], acc[i][j]);
        }
        __syncthreads();
    }
#pragma unroll
    for (int i = 0; i < 8; i++) {
        int gr = brow + row0 + i;
        if (gr >= M) continue;
#pragma unroll
        for (int j = 0; j < 8; j += 4) {
            int gc = bcol + col0 + j;
            if (gc >= N) continue;
            float4 v;
            v.x = acc[i][j + 0] + (bias ? bias[gc + 0] : 0.f);
            v.y = acc[i][j + 1] + (bias ? bias[gc + 1] : 0.f);
            v.z = acc[i][j + 2] + (bias ? bias[gc + 2] : 0.f);
            v.w = acc[i][j + 3] + (bias ? bias[gc + 3] : 0.f);
            *reinterpret_cast<float4*>(C + (size_t)gr * N + gc) = v;
        }
    }
}

// -------------------- per-(node,head) attention logits ---------------------
// alpha_s[n,h] = <h[n,h,:], a_src[h,:]> ; alpha_d likewise. One warp per (n,h).
__global__ void alpha_kernel(const float* __restrict__ h,
                             const float* __restrict__ asrc,
                             const float* __restrict__ adst,
                             int N, int C)
{
    int gw   = (blockIdx.x * blockDim.x + threadIdx.x) >> 5;
    int lane = threadIdx.x & 31;
    if (gw >= N * 4) return;
    int n = gw >> 2, hh = gw & 3;
    const float* hv = h + (size_t)n * 4 * C + (size_t)hh * C;
    float s = 0.f, d = 0.f;
    for (int c = lane; c < C; c += 32) {
        float v = hv[c];
        s = fmaf(v, asrc[hh * C + c], s);
        d = fmaf(v, adst[hh * C + c], d);
    }
#pragma unroll
    for (int o = 16; o; o >>= 1) {
        s += __shfl_down_sync(0xFFFFFFFFu, s, o);
        d += __shfl_down_sync(0xFFFFFFFFu, d, o);
    }
    if (lane == 0) { g_as[gw] = s; g_ad[gw] = d; }
}

// -------------------- edge pass 1: logits + segment max --------------------
__global__ void edge_pass1(const int* __restrict__ src,
                           const int* __restrict__ dst,
                           int E, int N)
{
    int e = blockIdx.x * blockDim.x + threadIdx.x;
    int Et = E + N;
    if (e >= Et) return;
    int s, d;
    if (e < E) { s = src[e]; d = dst[e]; } else { s = d = e - E; }
    float4 A = *reinterpret_cast<const float4*>(g_as + (size_t)s * 4);
    float4 D = *reinterpret_cast<const float4*>(g_ad + (size_t)d * 4);
    float v0 = A.x + D.x, v1 = A.y + D.y, v2 = A.z + D.z, v3 = A.w + D.w;
    v0 = v0 > 0.f ? v0 : 0.2f * v0;
    v1 = v1 > 0.f ? v1 : 0.2f * v1;
    v2 = v2 > 0.f ? v2 : 0.2f * v2;
    v3 = v3 > 0.f ? v3 : 0.2f * v3;
    unsigned* em = g_emax + (size_t)d * 4;
    atomicMax(&em[0], fenc(v0));
    atomicMax(&em[1], fenc(v1));
    atomicMax(&em[2], fenc(v2));
    atomicMax(&em[3], fenc(v3));
    *reinterpret_cast<float4*>(g_ebuf + (size_t)e * 4) = make_float4(v0, v1, v2, v3);
}

// -------------------- edge pass 2: exp, denom, weighted aggregate ----------
// One warp per edge; lanes stride the 4*C feature dim (coalesced gather+atomic).
template<int C>
__global__ void edge_pass2(const int* __restrict__ src,
                           const int* __restrict__ dst,
                           int E, int N,
                           const float* __restrict__ h,
                           float* __restrict__ agg)
{
    int gw   = (blockIdx.x * blockDim.x + threadIdx.x) >> 5;
    int lane = threadIdx.x & 31;
    int Et = E + N;
    if (gw >= Et) return;
    int s, d;
    if (gw < E) { s = src[gw]; d = dst[gw]; } else { s = d = gw - E; }
    float4 ev = *reinterpret_cast<const float4*>(g_ebuf + (size_t)gw * 4);
    const unsigned* em = g_emax + (size_t)d * 4;
    float x0 = expf(ev.x - fdec(em[0]));
    float x1 = expf(ev.y - fdec(em[1]));
    float x2 = expf(ev.z - fdec(em[2]));
    float x3 = expf(ev.w - fdec(em[3]));
    if (lane < 4) {
        float mine = (lane == 0) ? x0 : (lane == 1) ? x1 : (lane == 2) ? x2 : x3;
        atomicAdd(&g_esum[(size_t)d * 4 + lane], mine);
    }
    const float* hs = h + (size_t)s * (4 * C);
    float*       ag = agg + (size_t)d * (4 * C);
#pragma unroll
    for (int i = 0; i < (4 * C) / 32; i++) {
        int f  = lane + i * 32;
        int hh = f / C;
        float w = (hh == 0) ? x0 : (hh == 1) ? x1 : (hh == 2) ? x2 : x3;
        atomicAdd(&ag[f], w * hs[f]);
    }
}

// -------------------- layer-1 finalize: normalize + bias + ELU -------------
__global__ void finalize1(const float* __restrict__ b1, int N)
{
    int i = blockIdx.x * blockDim.x + threadIdx.x;
    if (i >= N * 128) return;
    int n = i >> 7, f = i & 127;
    float v = g_agg1[i] / (g_esum[n * 4 + (f >> 5)] + 1e-16f) + b1[f];
    g_hact[i] = v > 0.f ? v : expm1f(v);
}

// -------------------- layer-2 finalize: normalize + head-mean + bias -------
__global__ void finalize2(const float* __restrict__ b2, float* __restrict__ emb, int N)
{
    int i = blockIdx.x * blockDim.x + threadIdx.x;
    if (i >= N * 128) return;
    int n = i >> 7, c = i & 127;
    const float* ag = g_agg2 + (size_t)n * 512;
    const float* es = g_esum + (size_t)n * 4;
    float acc = 0.f;
#pragma unroll
    for (int hh = 0; hh < 4; hh++)
        acc += ag[hh * 128 + c] / (es[hh] + 1e-16f);
    emb[i] = 0.25f * acc + b2[c];
}

// ---------------------------------------------------------------------------
extern "C" void kernel_launch(void* const* d_in, const int* in_sizes, int n_in,
                              void* d_out, int out_size)
{
    const float* x      = (const float*)d_in[0];
    const int*   eidx   = (const int*)d_in[1];     // int32! (JAX x64 disabled)
    const float* W1     = (const float*)d_in[2];
    const float* a_src1 = (const float*)d_in[3];
    const float* a_dst1 = (const float*)d_in[4];
    const float* b1     = (const float*)d_in[5];
    const float* W2     = (const float*)d_in[6];
    const float* a_src2 = (const float*)d_in[7];
    const float* a_dst2 = (const float*)d_in[8];
    const float* b2     = (const float*)d_in[9];
    const float* W_lin  = (const float*)d_in[10];
    const float* b_lin  = (const float*)d_in[11];

    const int N = in_sizes[0] / 512;   // 100000
    const int E = in_sizes[1] / 2;     // 600000
    const int Et = E + N;              // 700000

    const int* src = eidx;
    const int* dst = eidx + E;

    float* out = (float*)d_out;                  // [N, 64]
    float* emb = (float*)d_out + (size_t)N * 64; // [N, 128]

    // device-global scratch addresses
    float* h1;   cudaGetSymbolAddress((void**)&h1,   g_h1);
    float* hact; cudaGetSymbolAddress((void**)&hact, g_hact);
    float* h2;   cudaGetSymbolAddress((void**)&h2,   g_h2);
    float* agg1; cudaGetSymbolAddress((void**)&agg1, g_agg1);
    float* agg2; cudaGetSymbolAddress((void**)&agg2, g_agg2);

    const int T = 256;
    dim3 g1((128 + 127) / 128, (N + 127) / 128);  // GEMM1: N=128
    dim3 g2((512 + 127) / 128, (N + 127) / 128);  // GEMM2: N=512
    dim3 g3((64  + 127) / 128, (N + 127) / 128);  // GEMM3: N=64

    int blk_alpha = (N * 4 * 32 + T - 1) / T;
    int blk_e1    = (Et + T - 1) / T;
    int blk_e2    = (int)(((long long)Et * 32 + T - 1) / T);
    int blk_nf    = (N * 128 + T - 1) / T;
    int blk_z1    = (N * 128 + T - 1) / T;
    int blk_z2    = (N * 512 + T - 1) / T;

    // ---------------- layer 1 ----------------
    sgemm128<<<g1, T>>>(x, W1, nullptr, h1, N, 128, 512);
    alpha_kernel<<<blk_alpha, T>>>(h1, a_src1, a_dst1, N, 32);
    zero_layer1<<<blk_z1, T>>>(N);
    edge_pass1<<<blk_e1, T>>>(src, dst, E, N);
    edge_pass2<32><<<blk_e2, T>>>(src, dst, E, N, h1, agg1);
    finalize1<<<blk_nf, T>>>(b1, N);

    // ---------------- layer 2 ----------------
    sgemm128<<<g2, T>>>(hact, W2, nullptr, h2, N, 512, 128);
    alpha_kernel<<<blk_alpha, T>>>(h2, a_src2, a_dst2, N, 128);
    zero_layer2<<<blk_z2, T>>>(N);
    edge_pass1<<<blk_e1, T>>>(src, dst, E, N);
    edge_pass2<128><<<blk_e2, T>>>(src, dst, E, N, h2, agg2);
    finalize2<<<blk_nf, T>>>(b2, emb, N);

    // ---------------- head ----------------
    sgemm128<<<g3, T>>>(emb, W_lin, b_lin, out, N, 64, 128);
}

// round 3
// speedup vs baseline: 1.4356x; 1.4356x over previous
#include <cuda_runtime.h>
#include <cuda_bf16.h>
#include <cstdint>

// ---------------------------------------------------------------------------
// GATNet: GATConv(512->4x32,concat)+ELU -> GATConv(128->4x128,mean) -> Linear
// CSR-by-destination formulation: no scatter atomics in the hot path.
// Output layout: [ out (N*64) | embeddings (N*128) ]
// edge_index is int32 on disk (JAX x64 disabled).
// ---------------------------------------------------------------------------

#define MAXN 100000
#define MAXE 600000
#define MAXET (MAXE + MAXN)   // edges incl. self loops

// -------------------- scratch (device globals; no allocs) ------------------
__device__ float g_h1[(size_t)MAXN * 128];    // GEMM1 output  [N, H*C1]
__device__ float g_hact[(size_t)MAXN * 128];  // layer-1 activated output
__device__ float g_h2[(size_t)MAXN * 512];    // GEMM2 output  [N, H*C2]
__device__ float g_as[(size_t)MAXN * 4];      // alpha_src per (node, head)
__device__ float g_ad[(size_t)MAXN * 4];      // alpha_dst per (node, head)
__device__ float g_esum[(size_t)MAXN * 4];    // softmax denominators
__device__ int   g_cnt[MAXN];                 // histogram, then scatter cursor
__device__ int   g_off[MAXN + 1];             // CSR row offsets (by dst)
__device__ int   g_bsum[1024];                // scan block sums
__device__ int   g_csrc[MAXET];               // CSR payload: src node id
__device__ float g_alpha[(size_t)MAXET * 4];  // per-CSR-slot exp(logit) (4 heads)

// -------------------- SGEMM: C[M,N] = A[M,K] @ B[K,N] (+bias) --------------
__global__ __launch_bounds__(256) void sgemm128(
    const float* __restrict__ A, const float* __restrict__ B,
    const float* __restrict__ bias, float* __restrict__ C,
    int M, int N, int K)
{
    __shared__ float As[16][128];
    __shared__ float Bs[16][128];
    const int tid  = threadIdx.x;
    const int brow = blockIdx.y * 128;
    const int bcol = blockIdx.x * 128;
    const int tr = tid >> 4, tc = tid & 15;
    const int row0 = tr * 8, col0 = tc * 8;

    float acc[8][8];
#pragma unroll
    for (int i = 0; i < 8; i++)
#pragma unroll
        for (int j = 0; j < 8; j++) acc[i][j] = 0.f;

    for (int k0 = 0; k0 < K; k0 += 16) {
#pragma unroll
        for (int i = 0; i < 2; i++) {
            int id = tid + i * 256;
            int r  = id >> 2;
            int c  = (id & 3) << 2;
            float4 v = make_float4(0.f, 0.f, 0.f, 0.f);
            int gr = brow + r;
            if (gr < M)
                v = *reinterpret_cast<const float4*>(A + (size_t)gr * K + k0 + c);
            As[c + 0][r] = v.x; As[c + 1][r] = v.y;
            As[c + 2][r] = v.z; As[c + 3][r] = v.w;
        }
#pragma unroll
        for (int i = 0; i < 2; i++) {
            int id = tid + i * 256;
            int r  = id >> 5;
            int c  = (id & 31) << 2;
            float4 v = make_float4(0.f, 0.f, 0.f, 0.f);
            int gc = bcol + c;
            if (gc < N)
                v = *reinterpret_cast<const float4*>(B + (size_t)(k0 + r) * N + gc);
            *reinterpret_cast<float4*>(&Bs[r][c]) = v;
        }
        __syncthreads();
#pragma unroll
        for (int k = 0; k < 16; k++) {
            float a[8], b[8];
#pragma unroll
            for (int j = 0; j < 8; j++) { a[j] = As[k][row0 + j]; b[j] = Bs[k][col0 + j]; }
#pragma unroll
            for (int i = 0; i < 8; i++)
#pragma unroll
                for (int j = 0; j < 8; j++) acc[i][j] = fmaf(a[i], b[j], acc[i][j]);
        }
        __syncthreads();
    }
#pragma unroll
    for (int i = 0; i < 8; i++) {
        int gr = brow + row0 + i;
        if (gr >= M) continue;
#pragma unroll
        for (int j = 0; j < 8; j += 4) {
            int gc = bcol + col0 + j;
            if (gc >= N) continue;
            float4 v;
            v.x = acc[i][j + 0] + (bias ? bias[gc + 0] : 0.f);
            v.y = acc[i][j + 1] + (bias ? bias[gc + 1] : 0.f);
            v.z = acc[i][j + 2] + (bias ? bias[gc + 2] : 0.f);
            v.w = acc[i][j + 3] + (bias ? bias[gc + 3] : 0.f);
            *reinterpret_cast<float4*>(C + (size_t)gr * N + gc) = v;
        }
    }
}

// -------------------- CSR build --------------------------------------------
__global__ void zero_cnt(int N) {
    int i = blockIdx.x * blockDim.x + threadIdx.x;
    if (i < N) g_cnt[i] = 0;
}
__global__ void hist_k(const int* __restrict__ dst, int E, int N) {
    int e = blockIdx.x * blockDim.x + threadIdx.x;
    if (e >= E + N) return;
    int d = (e < E) ? dst[e] : e - E;
    atomicAdd(&g_cnt[d], 1);
}
// block-level inclusive scan over 1024 elems -> exclusive offsets + block sums
__global__ __launch_bounds__(1024) void scan1(int N) {
    __shared__ int sh[1024];
    int i = blockIdx.x * 1024 + threadIdx.x;
    int v = (i < N) ? g_cnt[i] : 0;
    sh[threadIdx.x] = v;
    __syncthreads();
    for (int o = 1; o < 1024; o <<= 1) {
        int t = (threadIdx.x >= o) ? sh[threadIdx.x - o] : 0;
        __syncthreads();
        sh[threadIdx.x] += t;
        __syncthreads();
    }
    if (i < N) g_off[i] = sh[threadIdx.x] - v;     // block-local exclusive
    if (threadIdx.x == 1023) g_bsum[blockIdx.x] = sh[1023];
}
__global__ __launch_bounds__(1024) void scan2(int NB) {
    __shared__ int sh[1024];
    int v = (threadIdx.x < NB) ? g_bsum[threadIdx.x] : 0;
    sh[threadIdx.x] = v;
    __syncthreads();
    for (int o = 1; o < 1024; o <<= 1) {
        int t = (threadIdx.x >= o) ? sh[threadIdx.x - o] : 0;
        __syncthreads();
        sh[threadIdx.x] += t;
        __syncthreads();
    }
    if (threadIdx.x < NB) g_bsum[threadIdx.x] = sh[threadIdx.x] - v; // exclusive
}
__global__ void scan3(int N, int Et) {
    int i = blockIdx.x * blockDim.x + threadIdx.x;
    if (i < N) {
        int v = g_off[i] + g_bsum[i >> 10];
        g_off[i] = v;
        g_cnt[i] = v;    // scatter cursor
    }
    if (i == 0) g_off[N] = Et;
}
__global__ void scatter_k(const int* __restrict__ src, const int* __restrict__ dst,
                          int E, int N) {
    int e = blockIdx.x * blockDim.x + threadIdx.x;
    if (e >= E + N) return;
    int s, d;
    if (e < E) { s = src[e]; d = dst[e]; } else { s = d = e - E; }
    int p = atomicAdd(&g_cnt[d], 1);
    g_csrc[p] = s;
}

// -------------------- per-(node,head) attention logits ---------------------
__global__ void alpha_kernel(const float* __restrict__ h,
                             const float* __restrict__ asrc,
                             const float* __restrict__ adst,
                             int N, int C)
{
    int gw   = (blockIdx.x * blockDim.x + threadIdx.x) >> 5;
    int lane = threadIdx.x & 31;
    if (gw >= N * 4) return;
    int n = gw >> 2, hh = gw & 3;
    const float* hv = h + (size_t)n * 4 * C + (size_t)hh * C;
    float s = 0.f, d = 0.f;
    for (int c = lane; c < C; c += 32) {
        float v = hv[c];
        s = fmaf(v, asrc[hh * C + c], s);
        d = fmaf(v, adst[hh * C + c], d);
    }
#pragma unroll
    for (int o = 16; o; o >>= 1) {
        s += __shfl_down_sync(0xFFFFFFFFu, s, o);
        d += __shfl_down_sync(0xFFFFFFFFu, d, o);
    }
    if (lane == 0) { g_as[gw] = s; g_ad[gw] = d; }
}

// -------------------- per-node warp softmax over incoming edges ------------
__global__ void edge_softmax(int N)
{
    int gw   = (blockIdx.x * blockDim.x + threadIdx.x) >> 5;
    int lane = threadIdx.x & 31;
    if (gw >= N) return;
    int beg = g_off[gw], end = g_off[gw + 1];
    float4 D = *reinterpret_cast<const float4*>(g_ad + (size_t)gw * 4);
    float m0 = -1e30f, m1 = -1e30f, m2 = -1e30f, m3 = -1e30f;
    for (int j = beg + lane; j < end; j += 32) {
        int s = g_csrc[j];
        float4 A = *reinterpret_cast<const float4*>(g_as + (size_t)s * 4);
        float v0 = A.x + D.x, v1 = A.y + D.y, v2 = A.z + D.z, v3 = A.w + D.w;
        v0 = v0 > 0.f ? v0 : 0.2f * v0;
        v1 = v1 > 0.f ? v1 : 0.2f * v1;
        v2 = v2 > 0.f ? v2 : 0.2f * v2;
        v3 = v3 > 0.f ? v3 : 0.2f * v3;
        *reinterpret_cast<float4*>(g_alpha + (size_t)j * 4) = make_float4(v0, v1, v2, v3);
        m0 = fmaxf(m0, v0); m1 = fmaxf(m1, v1);
        m2 = fmaxf(m2, v2); m3 = fmaxf(m3, v3);
    }
#pragma unroll
    for (int o = 16; o; o >>= 1) {
        m0 = fmaxf(m0, __shfl_xor_sync(0xFFFFFFFFu, m0, o));
        m1 = fmaxf(m1, __shfl_xor_sync(0xFFFFFFFFu, m1, o));
        m2 = fmaxf(m2, __shfl_xor_sync(0xFFFFFFFFu, m2, o));
        m3 = fmaxf(m3, __shfl_xor_sync(0xFFFFFFFFu, m3, o));
    }
    float s0 = 0.f, s1 = 0.f, s2 = 0.f, s3 = 0.f;
    for (int j = beg + lane; j < end; j += 32) {
        float4 v = *reinterpret_cast<const float4*>(g_alpha + (size_t)j * 4);
        float x0 = expf(v.x - m0), x1 = expf(v.y - m1);
        float x2 = expf(v.z - m2), x3 = expf(v.w - m3);
        *reinterpret_cast<float4*>(g_alpha + (size_t)j * 4) = make_float4(x0, x1, x2, x3);
        s0 += x0; s1 += x1; s2 += x2; s3 += x3;
    }
#pragma unroll
    for (int o = 16; o; o >>= 1) {
        s0 += __shfl_xor_sync(0xFFFFFFFFu, s0, o);
        s1 += __shfl_xor_sync(0xFFFFFFFFu, s1, o);
        s2 += __shfl_xor_sync(0xFFFFFFFFu, s2, o);
        s3 += __shfl_xor_sync(0xFFFFFFFFu, s3, o);
    }
    if (lane == 0)
        *reinterpret_cast<float4*>(g_esum + (size_t)gw * 4) = make_float4(s0, s1, s2, s3);
}

// -------------------- layer-1 gather aggregate + bias + ELU ----------------
__global__ __launch_bounds__(128) void agg1_k(const float* __restrict__ b1, int N)
{
    int n = blockIdx.x;
    if (n >= N) return;
    int c = threadIdx.x;          // 0..127
    int h = c >> 5;
    int beg = g_off[n], end = g_off[n + 1];
    float r = 1.f / (g_esum[(size_t)n * 4 + h] + 1e-16f);
    float acc = 0.f;
    for (int j = beg; j < end; j++) {
        int s = g_csrc[j];
        float w = g_alpha[(size_t)j * 4 + h];
        acc = fmaf(w, g_h1[(size_t)s * 128 + c], acc);
    }
    float v = acc * r + b1[c];
    g_hact[(size_t)n * 128 + c] = v > 0.f ? v : expm1f(v);
}

// -------------------- layer-2 gather aggregate + head-mean + bias ----------
__global__ __launch_bounds__(128) void agg2_k(const float* __restrict__ b2,
                                              float* __restrict__ emb, int N)
{
    int n = blockIdx.x;
    if (n >= N) return;
    int c = threadIdx.x;          // 0..127
    int beg = g_off[n], end = g_off[n + 1];
    float4 es = *reinterpret_cast<const float4*>(g_esum + (size_t)n * 4);
    float r0 = 0.25f / (es.x + 1e-16f), r1 = 0.25f / (es.y + 1e-16f);
    float r2 = 0.25f / (es.z + 1e-16f), r3 = 0.25f / (es.w + 1e-16f);
    float acc = 0.f;
    for (int j = beg; j < end; j++) {
        int s = g_csrc[j];
        const float* row = g_h2 + (size_t)s * 512;
        float4 al = *reinterpret_cast<const float4*>(g_alpha + (size_t)j * 4);
        acc = fmaf(al.x * r0, row[c],       acc);
        acc = fmaf(al.y * r1, row[128 + c], acc);
        acc = fmaf(al.z * r2, row[256 + c], acc);
        acc = fmaf(al.w * r3, row[384 + c], acc);
    }
    emb[(size_t)n * 128 + c] = acc + b2[c];
}

// ---------------------------------------------------------------------------
extern "C" void kernel_launch(void* const* d_in, const int* in_sizes, int n_in,
                              void* d_out, int out_size)
{
    const float* x      = (const float*)d_in[0];
    const int*   eidx   = (const int*)d_in[1];     // int32
    const float* W1     = (const float*)d_in[2];
    const float* a_src1 = (const float*)d_in[3];
    const float* a_dst1 = (const float*)d_in[4];
    const float* b1     = (const float*)d_in[5];
    const float* W2     = (const float*)d_in[6];
    const float* a_src2 = (const float*)d_in[7];
    const float* a_dst2 = (const float*)d_in[8];
    const float* b2     = (const float*)d_in[9];
    const float* W_lin  = (const float*)d_in[10];
    const float* b_lin  = (const float*)d_in[11];

    const int N  = in_sizes[0] / 512;   // 100000
    const int E  = in_sizes[1] / 2;     // 600000
    const int Et = E + N;

    const int* src = eidx;
    const int* dst = eidx + E;

    float* out = (float*)d_out;                  // [N, 64]
    float* emb = (float*)d_out + (size_t)N * 64; // [N, 128]

    float* h1;   cudaGetSymbolAddress((void**)&h1,   g_h1);
    float* hact; cudaGetSymbolAddress((void**)&hact, g_hact);
    float* h2;   cudaGetSymbolAddress((void**)&h2,   g_h2);

    const int T = 256;
    dim3 g1((128 + 127) / 128, (N + 127) / 128);
    dim3 g2((512 + 127) / 128, (N + 127) / 128);
    dim3 g3((64  + 127) / 128, (N + 127) / 128);

    int blk_e     = (Et + T - 1) / T;
    int blk_n     = (N + T - 1) / T;
    int blk_alpha = (N * 4 * 32 + T - 1) / T;
    int blk_soft  = (N * 32 + T - 1) / T;
    int NB        = (N + 1023) / 1024;

    // ---- CSR build (by destination), reused by both layers ----
    zero_cnt<<<blk_n, T>>>(N);
    hist_k<<<blk_e, T>>>(dst, E, N);
    scan1<<<NB, 1024>>>(N);
    scan2<<<1, 1024>>>(NB);
    scan3<<<blk_n, T>>>(N, Et);
    scatter_k<<<blk_e, T>>>(src, dst, E, N);

    // ---- layer 1 ----
    sgemm128<<<g1, T>>>(x, W1, nullptr, h1, N, 128, 512);
    alpha_kernel<<<blk_alpha, T>>>(h1, a_src1, a_dst1, N, 32);
    edge_softmax<<<blk_soft, T>>>(N);
    agg1_k<<<N, 128>>>(b1, N);

    // ---- layer 2 ----
    sgemm128<<<g2, T>>>(hact, W2, nullptr, h2, N, 512, 128);
    alpha_kernel<<<blk_alpha, T>>>(h2, a_src2, a_dst2, N, 128);
    edge_softmax<<<blk_soft, T>>>(N);
    agg2_k<<<N, 128>>>(b2, emb, N);

    // ---- head ----
    sgemm128<<<g3, T>>>(emb, W_lin, b_lin, out, N, 64, 128);
}

// round 4
// speedup vs baseline: 2.2433x; 1.5627x over previous
#include <cuda_runtime.h>
#include <cuda_bf16.h>
#include <cstdint>

// ---------------------------------------------------------------------------
// GATNet, round 4:
//  - CSR-by-destination edge pipeline (round 3)
//  - layer-2 algebraic refactor: aggregate hact, then multiply by permuted W2
//  - all GEMMs on tensor cores: bf16 3-way split mma.sync (fp32-grade accuracy)
// Output layout: [ out (N*64) | embeddings (N*128) ]
// ---------------------------------------------------------------------------

#define MAXN 100000
#define MAXE 600000
#define MAXET (MAXE + MAXN)

// -------------------- scratch (device globals; no allocs) ------------------
__device__ float g_h1[(size_t)MAXN * 128];    // GEMM1 output
__device__ float g_hact[(size_t)MAXN * 128];  // layer-1 activated output
__device__ float g_aggn[(size_t)MAXN * 512];  // layer-2 normalized aggregate
__device__ float g_as[(size_t)MAXN * 4];
__device__ float g_ad[(size_t)MAXN * 4];
__device__ float g_esum[(size_t)MAXN * 4];
__device__ int   g_cnt[MAXN];
__device__ int   g_off[MAXN + 1];
__device__ int   g_bsum[1024];
__device__ int   g_csrc[MAXET];
__device__ float g_alpha[(size_t)MAXET * 4];
// pre-split / transposed weights (bf16 hi/lo), layout [N][K]
__device__ __nv_bfloat16 g_W1h[128 * 512],  g_W1l[128 * 512];
__device__ __nv_bfloat16 g_W2h[128 * 512],  g_W2l[128 * 512];   // permuted W2
__device__ __nv_bfloat16 g_WLh[64 * 128],   g_WLl[64 * 128];
__device__ float g_was[128 * 4], g_wad[128 * 4];                // W2·a_{src,dst}2

// -------------------- bf16 mma helper ---------------------------------------
__device__ __forceinline__ void mma16816(float* c, const uint32_t* a, const uint32_t* b) {
    asm volatile(
        "mma.sync.aligned.m16n8k16.row.col.f32.bf16.bf16.f32 "
        "{%0,%1,%2,%3}, {%4,%5,%6,%7}, {%8,%9}, {%0,%1,%2,%3};\n"
        : "+f"(c[0]), "+f"(c[1]), "+f"(c[2]), "+f"(c[3])
        : "r"(a[0]), "r"(a[1]), "r"(a[2]), "r"(a[3]), "r"(b[0]), "r"(b[1]));
}

// -------------------- tensor GEMM: C[M,N] = A[M,K] @ B[K,N] (+bias) --------
// A fp32 in gmem (split to bf16 hi/lo on the fly); B pre-split+transposed
// bf16 [N][K]. Tile 128x128, BK=32, 256 threads = 8 warps (2x4 warp grid).
// 3-way split: Ahi*Bhi + Ahi*Blo + Alo*Bhi  (error ~2^-18, fp32 accumulate).
__global__ __launch_bounds__(256) void gemm_bf16x3(
    const float* __restrict__ A,
    const __nv_bfloat16* __restrict__ Bth, const __nv_bfloat16* __restrict__ Btl,
    const float* __restrict__ bias, float* __restrict__ C,
    int M, int N, int K)
{
    __shared__ __nv_bfloat16 Ah[128][40];
    __shared__ __nv_bfloat16 Al[128][40];
    __shared__ __nv_bfloat16 Bh[128][40];
    __shared__ __nv_bfloat16 Bl[128][40];

    const int tid  = threadIdx.x;
    const int lane = tid & 31;
    const int wid  = tid >> 5;
    const int brow = blockIdx.y * 128;
    const int bcol = blockIdx.x * 128;
    const int moff = (wid >> 2) * 64;   // warp m offset (2 warp-rows)
    const int noff = (wid & 3) * 32;    // warp n offset (4 warp-cols)

    float acc[4][4][4];
#pragma unroll
    for (int i = 0; i < 4; i++)
#pragma unroll
        for (int j = 0; j < 4; j++)
#pragma unroll
            for (int q = 0; q < 4; q++) acc[i][j][q] = 0.f;

    const int ar  = tid >> 1;             // A tile row 0..127
    const int ac  = (tid & 1) * 16;       // A tile col 0 / 16
    const int agr = min(brow + ar, M - 1);
    const int bn  = tid >> 1;             // B tile n-row 0..127
    const int bk  = (tid & 1) * 16;       // B tile k 0 / 16
    const bool bvalid = (bcol + bn) < N;

    for (int k0 = 0; k0 < K; k0 += 32) {
        // ---- load + split A (16 fp32 per thread) ----
        {
            const float* ap = A + (size_t)agr * K + k0 + ac;
            float4 v0 = reinterpret_cast<const float4*>(ap)[0];
            float4 v1 = reinterpret_cast<const float4*>(ap)[1];
            float4 v2 = reinterpret_cast<const float4*>(ap)[2];
            float4 v3 = reinterpret_cast<const float4*>(ap)[3];
            float av[16] = {v0.x, v0.y, v0.z, v0.w, v1.x, v1.y, v1.z, v1.w,
                            v2.x, v2.y, v2.z, v2.w, v3.x, v3.y, v3.z, v3.w};
#pragma unroll
            for (int i = 0; i < 16; i += 2) {
                __nv_bfloat16 h0 = __float2bfloat16(av[i]);
                __nv_bfloat16 h1 = __float2bfloat16(av[i + 1]);
                __nv_bfloat16 l0 = __float2bfloat16(av[i]     - __bfloat162float(h0));
                __nv_bfloat16 l1 = __float2bfloat16(av[i + 1] - __bfloat162float(h1));
                __nv_bfloat162 ph; ph.x = h0; ph.y = h1;
                __nv_bfloat162 pl; pl.x = l0; pl.y = l1;
                *reinterpret_cast<__nv_bfloat162*>(&Ah[ar][ac + i]) = ph;
                *reinterpret_cast<__nv_bfloat162*>(&Al[ar][ac + i]) = pl;
            }
        }
        // ---- load B (16 bf16 hi + 16 lo per thread, already [N][K]) ----
        {
            if (bvalid) {
                const __nv_bfloat16* bph = Bth + (size_t)(bcol + bn) * K + k0 + bk;
                const __nv_bfloat16* bpl = Btl + (size_t)(bcol + bn) * K + k0 + bk;
                *reinterpret_cast<uint4*>(&Bh[bn][bk])     = reinterpret_cast<const uint4*>(bph)[0];
                *reinterpret_cast<uint4*>(&Bh[bn][bk + 8]) = reinterpret_cast<const uint4*>(bph)[1];
                *reinterpret_cast<uint4*>(&Bl[bn][bk])     = reinterpret_cast<const uint4*>(bpl)[0];
                *reinterpret_cast<uint4*>(&Bl[bn][bk + 8]) = reinterpret_cast<const uint4*>(bpl)[1];
            } else {
                uint4 z = make_uint4(0, 0, 0, 0);
                *reinterpret_cast<uint4*>(&Bh[bn][bk])     = z;
                *reinterpret_cast<uint4*>(&Bh[bn][bk + 8]) = z;
                *reinterpret_cast<uint4*>(&Bl[bn][bk])     = z;
                *reinterpret_cast<uint4*>(&Bl[bn][bk + 8]) = z;
            }
        }
        __syncthreads();

#pragma unroll
        for (int ks = 0; ks < 32; ks += 16) {
            const int kf = ks + (lane & 3) * 2;
            uint32_t bhf[4][2], blf[4][2];
#pragma unroll
            for (int in = 0; in < 4; in++) {
                int n = noff + in * 8 + (lane >> 2);
                bhf[in][0] = *reinterpret_cast<const uint32_t*>(&Bh[n][kf]);
                bhf[in][1] = *reinterpret_cast<const uint32_t*>(&Bh[n][kf + 8]);
                blf[in][0] = *reinterpret_cast<const uint32_t*>(&Bl[n][kf]);
                blf[in][1] = *reinterpret_cast<const uint32_t*>(&Bl[n][kf + 8]);
            }
#pragma unroll
            for (int im = 0; im < 4; im++) {
                int m = moff + im * 16 + (lane >> 2);
                uint32_t ahf[4], alf[4];
                ahf[0] = *reinterpret_cast<const uint32_t*>(&Ah[m][kf]);
                ahf[1] = *reinterpret_cast<const uint32_t*>(&Ah[m + 8][kf]);
                ahf[2] = *reinterpret_cast<const uint32_t*>(&Ah[m][kf + 8]);
                ahf[3] = *reinterpret_cast<const uint32_t*>(&Ah[m + 8][kf + 8]);
                alf[0] = *reinterpret_cast<const uint32_t*>(&Al[m][kf]);
                alf[1] = *reinterpret_cast<const uint32_t*>(&Al[m + 8][kf]);
                alf[2] = *reinterpret_cast<const uint32_t*>(&Al[m][kf + 8]);
                alf[3] = *reinterpret_cast<const uint32_t*>(&Al[m + 8][kf + 8]);
#pragma unroll
                for (int in = 0; in < 4; in++) {
                    mma16816(acc[im][in], ahf, bhf[in]);
                    mma16816(acc[im][in], ahf, blf[in]);
                    mma16816(acc[im][in], alf, bhf[in]);
                }
            }
        }
        __syncthreads();
    }

    // ---- epilogue ----
#pragma unroll
    for (int im = 0; im < 4; im++) {
#pragma unroll
        for (int in = 0; in < 4; in++) {
            int gr = brow + moff + im * 16 + (lane >> 2);
            int gc = bcol + noff + in * 8 + (lane & 3) * 2;
            if (gc >= N) continue;
            float bx = bias ? bias[gc] : 0.f;
            float by = bias ? bias[gc + 1] : 0.f;
            if (gr < M) {
                float2 v = make_float2(acc[im][in][0] + bx, acc[im][in][1] + by);
                *reinterpret_cast<float2*>(C + (size_t)gr * N + gc) = v;
            }
            if (gr + 8 < M) {
                float2 v = make_float2(acc[im][in][2] + bx, acc[im][in][3] + by);
                *reinterpret_cast<float2*>(C + (size_t)(gr + 8) * N + gc) = v;
            }
        }
    }
}

// -------------------- weight prep kernels ----------------------------------
// transpose + split: Bt[n][k] = split(W[k*N + n])
__global__ void split_w(const float* __restrict__ W,
                        __nv_bfloat16* __restrict__ hi, __nv_bfloat16* __restrict__ lo,
                        int K, int N)
{
    int idx = blockIdx.x * blockDim.x + threadIdx.x;
    if (idx >= K * N) return;
    int k = idx / N, n = idx % N;
    float v = W[idx];
    __nv_bfloat16 h = __float2bfloat16(v);
    hi[(size_t)n * K + k] = h;
    lo[(size_t)n * K + k] = __float2bfloat16(v - __bfloat162float(h));
}
// permuted W2: row = h*128+k, col c: val = W2[k][h*128+c]; store [c][row]
__global__ void split_w2p(const float* __restrict__ W2)
{
    int idx = blockIdx.x * blockDim.x + threadIdx.x;   // 512*128
    if (idx >= 512 * 128) return;
    int row = idx >> 7, c = idx & 127;
    int h = row >> 7, k = row & 127;
    float v = W2[(size_t)k * 512 + h * 128 + c];
    __nv_bfloat16 hb = __float2bfloat16(v);
    g_W2h[(size_t)c * 512 + row] = hb;
    g_W2l[(size_t)c * 512 + row] = __float2bfloat16(v - __bfloat162float(hb));
}
// wa_s[k][h] = sum_c W2[k][h*128+c] * a_src2[h][c]  (and dst)
__global__ void build_wa(const float* __restrict__ W2,
                         const float* __restrict__ as2, const float* __restrict__ ad2)
{
    int idx = blockIdx.x * blockDim.x + threadIdx.x;   // 128*4
    if (idx >= 128 * 4) return;
    int k = idx >> 2, h = idx & 3;
    float ss = 0.f, sd = 0.f;
    for (int c = 0; c < 128; c++) {
        float w = W2[(size_t)k * 512 + h * 128 + c];
        ss = fmaf(w, as2[h * 128 + c], ss);
        sd = fmaf(w, ad2[h * 128 + c], sd);
    }
    g_was[k * 4 + h] = ss;
    g_wad[k * 4 + h] = sd;
}

// -------------------- CSR build --------------------------------------------
__global__ void zero_cnt(int N) {
    int i = blockIdx.x * blockDim.x + threadIdx.x;
    if (i < N) g_cnt[i] = 0;
}
__global__ void hist_k(const int* __restrict__ dst, int E, int N) {
    int e = blockIdx.x * blockDim.x + threadIdx.x;
    if (e >= E + N) return;
    int d = (e < E) ? dst[e] : e - E;
    atomicAdd(&g_cnt[d], 1);
}
__global__ __launch_bounds__(1024) void scan1(int N) {
    __shared__ int sh[1024];
    int i = blockIdx.x * 1024 + threadIdx.x;
    int v = (i < N) ? g_cnt[i] : 0;
    sh[threadIdx.x] = v;
    __syncthreads();
    for (int o = 1; o < 1024; o <<= 1) {
        int t = (threadIdx.x >= o) ? sh[threadIdx.x - o] : 0;
        __syncthreads();
        sh[threadIdx.x] += t;
        __syncthreads();
    }
    if (i < N) g_off[i] = sh[threadIdx.x] - v;
    if (threadIdx.x == 1023) g_bsum[blockIdx.x] = sh[1023];
}
__global__ __launch_bounds__(1024) void scan2(int NB) {
    __shared__ int sh[1024];
    int v = (threadIdx.x < NB) ? g_bsum[threadIdx.x] : 0;
    sh[threadIdx.x] = v;
    __syncthreads();
    for (int o = 1; o < 1024; o <<= 1) {
        int t = (threadIdx.x >= o) ? sh[threadIdx.x - o] : 0;
        __syncthreads();
        sh[threadIdx.x] += t;
        __syncthreads();
    }
    if (threadIdx.x < NB) g_bsum[threadIdx.x] = sh[threadIdx.x] - v;
}
__global__ void scan3(int N, int Et) {
    int i = blockIdx.x * blockDim.x + threadIdx.x;
    if (i < N) {
        int v = g_off[i] + g_bsum[i >> 10];
        g_off[i] = v;
        g_cnt[i] = v;
    }
    if (i == 0) g_off[N] = Et;
}
__global__ void scatter_k(const int* __restrict__ src, const int* __restrict__ dst,
                          int E, int N) {
    int e = blockIdx.x * blockDim.x + threadIdx.x;
    if (e >= E + N) return;
    int s, d;
    if (e < E) { s = src[e]; d = dst[e]; } else { s = d = e - E; }
    int p = atomicAdd(&g_cnt[d], 1);
    g_csrc[p] = s;
}

// -------------------- layer-1 attention logits (from h1) -------------------
__global__ void alpha_kernel(const float* __restrict__ h,
                             const float* __restrict__ asrc,
                             const float* __restrict__ adst,
                             int N, int C)
{
    int gw   = (blockIdx.x * blockDim.x + threadIdx.x) >> 5;
    int lane = threadIdx.x & 31;
    if (gw >= N * 4) return;
    int n = gw >> 2, hh = gw & 3;
    const float* hv = h + (size_t)n * 4 * C + (size_t)hh * C;
    float s = 0.f, d = 0.f;
    for (int c = lane; c < C; c += 32) {
        float v = hv[c];
        s = fmaf(v, asrc[hh * C + c], s);
        d = fmaf(v, adst[hh * C + c], d);
    }
#pragma unroll
    for (int o = 16; o; o >>= 1) {
        s += __shfl_down_sync(0xFFFFFFFFu, s, o);
        d += __shfl_down_sync(0xFFFFFFFFu, d, o);
    }
    if (lane == 0) { g_as[gw] = s; g_ad[gw] = d; }
}

// -------------------- layer-2 attention logits (deferred via wa) -----------
__global__ void alpha2_kernel(const float* __restrict__ hact, int N)
{
    int gw   = (blockIdx.x * blockDim.x + threadIdx.x) >> 5;
    int lane = threadIdx.x & 31;
    if (gw >= N) return;
    const float* hv = hact + (size_t)gw * 128;
    float s0 = 0.f, s1 = 0.f, s2 = 0.f, s3 = 0.f;
    float d0 = 0.f, d1 = 0.f, d2 = 0.f, d3 = 0.f;
    for (int k = lane; k < 128; k += 32) {
        float v = hv[k];
        float4 ws = *reinterpret_cast<const float4*>(&g_was[k * 4]);
        float4 wd = *reinterpret_cast<const float4*>(&g_wad[k * 4]);
        s0 = fmaf(v, ws.x, s0); s1 = fmaf(v, ws.y, s1);
        s2 = fmaf(v, ws.z, s2); s3 = fmaf(v, ws.w, s3);
        d0 = fmaf(v, wd.x, d0); d1 = fmaf(v, wd.y, d1);
        d2 = fmaf(v, wd.z, d2); d3 = fmaf(v, wd.w, d3);
    }
#pragma unroll
    for (int o = 16; o; o >>= 1) {
        s0 += __shfl_xor_sync(0xFFFFFFFFu, s0, o);
        s1 += __shfl_xor_sync(0xFFFFFFFFu, s1, o);
        s2 += __shfl_xor_sync(0xFFFFFFFFu, s2, o);
        s3 += __shfl_xor_sync(0xFFFFFFFFu, s3, o);
        d0 += __shfl_xor_sync(0xFFFFFFFFu, d0, o);
        d1 += __shfl_xor_sync(0xFFFFFFFFu, d1, o);
        d2 += __shfl_xor_sync(0xFFFFFFFFu, d2, o);
        d3 += __shfl_xor_sync(0xFFFFFFFFu, d3, o);
    }
    if (lane == 0) {
        *reinterpret_cast<float4*>(&g_as[(size_t)gw * 4]) = make_float4(s0, s1, s2, s3);
        *reinterpret_cast<float4*>(&g_ad[(size_t)gw * 4]) = make_float4(d0, d1, d2, d3);
    }
}

// -------------------- per-node warp softmax over incoming edges ------------
__global__ void edge_softmax(int N)
{
    int gw   = (blockIdx.x * blockDim.x + threadIdx.x) >> 5;
    int lane = threadIdx.x & 31;
    if (gw >= N) return;
    int beg = g_off[gw], end = g_off[gw + 1];
    float4 D = *reinterpret_cast<const float4*>(g_ad + (size_t)gw * 4);
    float m0 = -1e30f, m1 = -1e30f, m2 = -1e30f, m3 = -1e30f;
    for (int j = beg + lane; j < end; j += 32) {
        int s = g_csrc[j];
        float4 A = *reinterpret_cast<const float4*>(g_as + (size_t)s * 4);
        float v0 = A.x + D.x, v1 = A.y + D.y, v2 = A.z + D.z, v3 = A.w + D.w;
        v0 = v0 > 0.f ? v0 : 0.2f * v0;
        v1 = v1 > 0.f ? v1 : 0.2f * v1;
        v2 = v2 > 0.f ? v2 : 0.2f * v2;
        v3 = v3 > 0.f ? v3 : 0.2f * v3;
        *reinterpret_cast<float4*>(g_alpha + (size_t)j * 4) = make_float4(v0, v1, v2, v3);
        m0 = fmaxf(m0, v0); m1 = fmaxf(m1, v1);
        m2 = fmaxf(m2, v2); m3 = fmaxf(m3, v3);
    }
#pragma unroll
    for (int o = 16; o; o >>= 1) {
        m0 = fmaxf(m0, __shfl_xor_sync(0xFFFFFFFFu, m0, o));
        m1 = fmaxf(m1, __shfl_xor_sync(0xFFFFFFFFu, m1, o));
        m2 = fmaxf(m2, __shfl_xor_sync(0xFFFFFFFFu, m2, o));
        m3 = fmaxf(m3, __shfl_xor_sync(0xFFFFFFFFu, m3, o));
    }
    float s0 = 0.f, s1 = 0.f, s2 = 0.f, s3 = 0.f;
    for (int j = beg + lane; j < end; j += 32) {
        float4 v = *reinterpret_cast<const float4*>(g_alpha + (size_t)j * 4);
        float x0 = expf(v.x - m0), x1 = expf(v.y - m1);
        float x2 = expf(v.z - m2), x3 = expf(v.w - m3);
        *reinterpret_cast<float4*>(g_alpha + (size_t)j * 4) = make_float4(x0, x1, x2, x3);
        s0 += x0; s1 += x1; s2 += x2; s3 += x3;
    }
#pragma unroll
    for (int o = 16; o; o >>= 1) {
        s0 += __shfl_xor_sync(0xFFFFFFFFu, s0, o);
        s1 += __shfl_xor_sync(0xFFFFFFFFu, s1, o);
        s2 += __shfl_xor_sync(0xFFFFFFFFu, s2, o);
        s3 += __shfl_xor_sync(0xFFFFFFFFu, s3, o);
    }
    if (lane == 0)
        *reinterpret_cast<float4*>(g_esum + (size_t)gw * 4) = make_float4(s0, s1, s2, s3);
}

// -------------------- layer-1 gather aggregate + bias + ELU ----------------
__global__ __launch_bounds__(128) void agg1_k(const float* __restrict__ b1, int N)
{
    int n = blockIdx.x;
    if (n >= N) return;
    int c = threadIdx.x;
    int h = c >> 5;
    int beg = g_off[n], end = g_off[n + 1];
    float r = 1.f / (g_esum[(size_t)n * 4 + h] + 1e-16f);
    float acc = 0.f;
    for (int j = beg; j < end; j++) {
        int s = g_csrc[j];
        float w = g_alpha[(size_t)j * 4 + h];
        acc = fmaf(w, g_h1[(size_t)s * 128 + c], acc);
    }
    float v = acc * r + b1[c];
    g_hact[(size_t)n * 128 + c] = v > 0.f ? v : expm1f(v);
}

// -------------------- layer-2 gather aggregate (of hact), normalized -------
__global__ __launch_bounds__(128) void agg2n_k(int N)
{
    int n = blockIdx.x;
    if (n >= N) return;
    int k = threadIdx.x;
    int beg = g_off[n], end = g_off[n + 1];
    float a0 = 0.f, a1 = 0.f, a2 = 0.f, a3 = 0.f;
    for (int j = beg; j < end; j++) {
        int s = g_csrc[j];
        float4 al = *reinterpret_cast<const float4*>(g_alpha + (size_t)j * 4);
        float v = g_hact[(size_t)s * 128 + k];
        a0 = fmaf(al.x, v, a0); a1 = fmaf(al.y, v, a1);
        a2 = fmaf(al.z, v, a2); a3 = fmaf(al.w, v, a3);
    }
    float4 es = *reinterpret_cast<const float4*>(g_esum + (size_t)n * 4);
    float* o = g_aggn + (size_t)n * 512;
    o[k]       = a0 * (0.25f / (es.x + 1e-16f));
    o[128 + k] = a1 * (0.25f / (es.y + 1e-16f));
    o[256 + k] = a2 * (0.25f / (es.z + 1e-16f));
    o[384 + k] = a3 * (0.25f / (es.w + 1e-16f));
}

// ---------------------------------------------------------------------------
extern "C" void kernel_launch(void* const* d_in, const int* in_sizes, int n_in,
                              void* d_out, int out_size)
{
    const float* x      = (const float*)d_in[0];
    const int*   eidx   = (const int*)d_in[1];     // int32
    const float* W1     = (const float*)d_in[2];
    const float* a_src1 = (const float*)d_in[3];
    const float* a_dst1 = (const float*)d_in[4];
    const float* b1     = (const float*)d_in[5];
    const float* W2     = (const float*)d_in[6];
    const float* a_src2 = (const float*)d_in[7];
    const float* a_dst2 = (const float*)d_in[8];
    const float* b2     = (const float*)d_in[9];
    const float* W_lin  = (const float*)d_in[10];
    const float* b_lin  = (const float*)d_in[11];

    const int N  = in_sizes[0] / 512;   // 100000
    const int E  = in_sizes[1] / 2;     // 600000
    const int Et = E + N;

    const int* src = eidx;
    const int* dst = eidx + E;

    float* out = (float*)d_out;                  // [N, 64]
    float* emb = (float*)d_out + (size_t)N * 64; // [N, 128]

    float* h1;   cudaGetSymbolAddress((void**)&h1,   g_h1);
    float* hact; cudaGetSymbolAddress((void**)&hact, g_hact);
    float* aggn; cudaGetSymbolAddress((void**)&aggn, g_aggn);
    __nv_bfloat16 *w1h, *w1l, *w2h, *w2l, *wlh, *wll;
    cudaGetSymbolAddress((void**)&w1h, g_W1h); cudaGetSymbolAddress((void**)&w1l, g_W1l);
    cudaGetSymbolAddress((void**)&w2h, g_W2h); cudaGetSymbolAddress((void**)&w2l, g_W2l);
    cudaGetSymbolAddress((void**)&wlh, g_WLh); cudaGetSymbolAddress((void**)&wll, g_WLl);

    const int T = 256;
    dim3 gg(1, (N + 127) / 128);          // all GEMMs: N<=128 -> grid.x = 1

    int blk_e     = (Et + T - 1) / T;
    int blk_n     = (N + T - 1) / T;
    int blk_alpha = (N * 4 * 32 + T - 1) / T;
    int blk_soft  = (N * 32 + T - 1) / T;
    int NB        = (N + 1023) / 1024;

    // ---- weight prep (tiny) ----
    split_w<<<(512 * 128 + T - 1) / T, T>>>(W1, w1h, w1l, 512, 128);
    split_w2p<<<(512 * 128 + T - 1) / T, T>>>(W2);
    split_w<<<(128 * 64 + T - 1) / T, T>>>(W_lin, wlh, wll, 128, 64);
    build_wa<<<2, T>>>(W2, a_src2, a_dst2);

    // ---- CSR build (by destination), reused by both layers ----
    zero_cnt<<<blk_n, T>>>(N);
    hist_k<<<blk_e, T>>>(dst, E, N);
    scan1<<<NB, 1024>>>(N);
    scan2<<<1, 1024>>>(NB);
    scan3<<<blk_n, T>>>(N, Et);
    scatter_k<<<blk_e, T>>>(src, dst, E, N);

    // ---- layer 1 ----
    gemm_bf16x3<<<gg, T>>>(x, w1h, w1l, nullptr, h1, N, 128, 512);
    alpha_kernel<<<blk_alpha, T>>>(h1, a_src1, a_dst1, N, 32);
    edge_softmax<<<blk_soft, T>>>(N);
    agg1_k<<<N, 128>>>(b1, N);

    // ---- layer 2 (deferred W2) ----
    alpha2_kernel<<<blk_soft, T>>>(hact, N);
    edge_softmax<<<blk_soft, T>>>(N);
    agg2n_k<<<N, 128>>>(N);
    gemm_bf16x3<<<gg, T>>>(aggn, w2h, w2l, b2, emb, N, 128, 512);

    // ---- head ----
    gemm_bf16x3<<<gg, T>>>(emb, wlh, wll, b_lin, out, N, 64, 128);
}